// round 11
// baseline (speedup 1.0000x reference)
#include <cuda_runtime.h>
#include <cuda_fp16.h>
#include <stdint.h>

// ---------------- problem constants ----------------
#define TSTEPS 512
#define BSZ    256
#define NIN    128
#define NHID   512
#define NOUT   10
#define DTc    0.042f
#define GAMc   2.7f
#define EPSc   4.7f

// ---------------- kernel config ----------------
#define NCTA    128          // 16 M-tiles(16 rows) x 8 N-tiles(64 cols)
#define CLUSTER 8            // one mi group = one cluster
#define KW      8            // warps; each = m16 x n64, k-slice of 128 (state part)
#define THREADS (KW*32)      // 256
#define JPW     8            // k16-blocks per warp
#define PS      68           // partial row stride (words, 16B-aligned rows)

// ---------------- device scratch ----------------
// fp16 state, R6-proven layout: row-major [256 rows][32 blocks of 16 cols];
// within a block, col-pair p (cols 2p,2p+1) at u32 position perm(p):
//   perm(p) = p<4 ? 2p : 2(p-4)+1   -> consumer lane c LDG.64 reads pairs {c, 4+c}
__device__ unsigned g_Hz[2][BSZ*256];
__device__ unsigned g_Hy[2][BSZ*256];
__device__ float    g_preX[(size_t)NCTA*TSTEPS*16*64];  // x@Wx + bias, per-CTA patches
__device__ float    g_hyf[BSZ*NHID];                    // final hy (fp32)

// ---------------- helpers ----------------
__device__ __forceinline__ float fast_tanh(float v) {
    float e = __expf(2.0f * v);
    return 1.0f - __fdividef(2.0f, e + 1.0f);
}
__device__ __forceinline__ unsigned pack_h2(float lo, float hi) {
    __half2 h = __floats2half2_rn(lo, hi);
    return *reinterpret_cast<unsigned*>(&h);
}
__device__ __forceinline__ void mma_f16(float* d,
                                        unsigned a0, unsigned a1, unsigned a2, unsigned a3,
                                        unsigned b0, unsigned b1) {
    asm volatile("mma.sync.aligned.m16n8k16.row.col.f32.f16.f16.f32 "
                 "{%0,%1,%2,%3}, {%4,%5,%6,%7}, {%8,%9}, {%0,%1,%2,%3};"
                 : "+f"(d[0]), "+f"(d[1]), "+f"(d[2]), "+f"(d[3])
                 : "r"(a0), "r"(a1), "r"(a2), "r"(a3), "r"(b0), "r"(b1));
}
__device__ __forceinline__ float2 ldcg2(const float* p) {
    return __ldcg(reinterpret_cast<const float2*>(p));
}
// remote arrive on cluster CTA `rank`'s mbar at same smem offset (release, cluster scope)
__device__ __forceinline__ void mbar_arrive_rank(unsigned addr, unsigned rank) {
    asm volatile(
        "{\n\t.reg .b32 ra;\n\t"
        "mapa.shared::cluster.u32 ra, %0, %1;\n\t"
        "mbarrier.arrive.release.cluster.shared::cluster.b64 _, [ra];\n\t"
        "}" :: "r"(addr), "r"(rank) : "memory");
}
// wait local mbar phase parity (acquire, cluster scope); HW-sleep try_wait
__device__ __forceinline__ void mbar_wait(unsigned addr, unsigned parity) {
    asm volatile(
        "{\n\t.reg .pred P;\n\t"
        "WAIT_LOOP_%=:\n\t"
        "mbarrier.try_wait.parity.acquire.cluster.shared::cta.b64 P, [%0], %1, 0x989680;\n\t"
        "@P bra.uni WAIT_DONE_%=;\n\t"
        "bra.uni WAIT_LOOP_%=;\n\t"
        "WAIT_DONE_%=:\n\t}"
        :: "r"(addr), "r"(parity) : "memory");
}

// ================= single persistent cluster kernel =================
__global__ void __launch_bounds__(THREADS, 1) __cluster_dims__(CLUSTER, 1, 1)
cornn_persist(const float* __restrict__ x, const float* __restrict__ W,
              const float* __restrict__ bias,
              const float* __restrict__ Wout, const float* __restrict__ bout,
              float* __restrict__ out) {
    __shared__ float Part[KW * 16 * PS];
    __shared__ __align__(8) unsigned long long mbar;

    const int tid  = threadIdx.x;
    const int cta  = blockIdx.x;
    const int mi   = cta >> 3;            // 0..15 : 16 batch rows
    const int ni   = cta & 7;             // 0..7  : 64 cols
    const int lane = tid & 31;
    const int warp = tid >> 5;            // 0..7
    const int rr   = lane >> 2;           // 0..7
    const int cc   = 2 * (lane & 3);

    const unsigned mbaddr = (unsigned)__cvta_generic_to_shared(&mbar);

    // ---- mbar init (count = 8 CTAs x 8 warps); cluster arrive (wait later) ----
    if (tid == 0) {
        asm volatile("mbarrier.init.shared.b64 [%0], %1;" :: "r"(mbaddr), "r"(64u) : "memory");
    }
    __syncthreads();
    asm volatile("barrier.cluster.arrive.aligned;" ::: "memory");

    // ================= phase 1: preX[t] = x_t @ W[0:128] + b (own patches) =================
    {
        unsigned xb0[JPW][8], xb1[JPW][8];
        const int n = ni * 64 + rr;
#pragma unroll
        for (int j = 0; j < JPW; ++j) {
            const int k0 = j * 16 + cc;
#pragma unroll
            for (int nf = 0; nf < 8; ++nf) {
                const float* wp = W + (size_t)k0 * NHID + n + nf * 8;
                xb0[j][nf] = pack_h2(wp[0],        wp[NHID]);
                xb1[j][nf] = pack_h2(wp[8 * NHID], wp[9 * NHID]);
            }
        }
        float bc[8][2];
#pragma unroll
        for (int nf = 0; nf < 8; ++nf) {
            int col = ni * 64 + nf * 8 + cc;
            bc[nf][0] = bias[col];
            bc[nf][1] = bias[col + 1];
        }
        const int brow = mi * 16 + rr;
        for (int i = 0; i < TSTEPS / KW; ++i) {
            const int t = warp + KW * i;
            float acc[8][4];
#pragma unroll
            for (int nf = 0; nf < 8; ++nf) {
                acc[nf][0] = bc[nf][0]; acc[nf][1] = bc[nf][1];
                acc[nf][2] = bc[nf][0]; acc[nf][3] = bc[nf][1];
            }
            const float* rx0 = x + ((size_t)t * BSZ + brow) * NIN + cc;
            const float* rx1 = rx0 + 8 * NIN;
#pragma unroll
            for (int j = 0; j < JPW; ++j) {
                float2 v0l = ldcg2(rx0 + j * 16), v0h = ldcg2(rx0 + j * 16 + 8);
                float2 v1l = ldcg2(rx1 + j * 16), v1h = ldcg2(rx1 + j * 16 + 8);
                unsigned a0 = pack_h2(v0l.x, v0l.y), a2 = pack_h2(v0h.x, v0h.y);
                unsigned a1 = pack_h2(v1l.x, v1l.y), a3 = pack_h2(v1h.x, v1h.y);
#pragma unroll
                for (int nf = 0; nf < 8; ++nf)
                    mma_f16(acc[nf], a0, a1, a2, a3, xb0[j][nf], xb1[j][nf]);
            }
            float* dst = g_preX + (size_t)(cta * TSTEPS + t) * (16 * 64);
#pragma unroll
            for (int nf = 0; nf < 8; ++nf) {
                int co = nf * 8 + cc;
                __stcg((float2*)(dst + rr * 64 + co),       make_float2(acc[nf][0], acc[nf][1]));
                __stcg((float2*)(dst + (rr + 8) * 64 + co), make_float2(acc[nf][2], acc[nf][3]));
            }
        }
    }

    // ================= init: zero fp16 state (buffer 0) =================
    const int srow = tid >> 4;                  // 0..15
    const int scol = (tid & 15) * 4;            // 0..60
    const int grow = mi * 16 + srow;
    const int gcol = ni * 64 + scol;
    const int blk  = gcol >> 4;
    const int pp   = (gcol & 15) >> 1;          // 0,2,4,6
    const int pos0 = (pp < 4) ? 2 * pp : 2 * pp - 7;
    const int pos1 = ((pp + 1) < 4) ? 2 * (pp + 1) : 2 * (pp + 1) - 7;
    const int hbase = grow * 256 + blk * 8;

    __stcg(&g_Hz[0][hbase + pos0], 0u);  __stcg(&g_Hz[0][hbase + pos1], 0u);
    __stcg(&g_Hy[0][hbase + pos0], 0u);  __stcg(&g_Hy[0][hbase + pos1], 0u);
    __syncwarp();

    // all cluster mbars initialized before any remote arrive
    asm volatile("barrier.cluster.wait.aligned;" ::: "memory");
    if (lane == 0) {
#pragma unroll
        for (unsigned r = 0; r < CLUSTER; ++r) mbar_arrive_rank(mbaddr, r);  // phase 0: state t=0
    }

    // ---- main-loop B fragments: W rows 128 + warp*128 .. +128 ----
    unsigned wb0[JPW][8], wb1[JPW][8];
    {
        const int n = ni * 64 + rr;
#pragma unroll
        for (int j = 0; j < JPW; ++j) {
            const int k0 = 128 + warp * 128 + j * 16 + cc;
#pragma unroll
            for (int nf = 0; nf < 8; ++nf) {
                const float* wp = W + (size_t)k0 * NHID + n + nf * 8;
                wb0[j][nf] = pack_h2(wp[0],        wp[NHID]);
                wb1[j][nf] = pack_h2(wp[8 * NHID], wp[9 * NHID]);
            }
        }
    }

    // consumer A-fragment base (same state layout as R6)
    const int hoff = (mi * 16 + rr) * 256 + (warp & 3) * 64 + 2 * (lane & 3);

    float hyr[4] = {0, 0, 0, 0}, hzr[4] = {0, 0, 0, 0};

    // ================= recurrence =================
    for (int t = 0; t < TSTEPS; ++t) {
        const int rb = t & 1, wbuf = rb ^ 1;

        // prefetch CTA-private preX patch
        float4 px = __ldcg((const float4*)(g_preX +
                         ((size_t)(cta * TSTEPS + t) * 16 + srow) * 64 + scol));

        // wait: phase t complete (all 64 producer-warp arrivals of this mi group)
        if (lane == 0) mbar_wait(mbaddr, (unsigned)(t & 1));
        __syncwarp();

        const unsigned* hp = ((warp < 4) ? g_Hz[rb] : g_Hy[rb]) + hoff;

        float acc[8][4];
#pragma unroll
        for (int nf = 0; nf < 8; ++nf)
#pragma unroll
            for (int c = 0; c < 4; ++c) acc[nf][c] = 0.f;

#pragma unroll
        for (int j = 0; j < JPW; ++j) {
            const unsigned* q = hp + j * 8;
            uint2 u0 = __ldcg((const uint2*)(q));
            uint2 u1 = __ldcg((const uint2*)(q + 8 * 256));
#pragma unroll
            for (int nf = 0; nf < 8; ++nf)
                mma_f16(acc[nf], u0.x, u1.x, u0.y, u1.y, wb0[j][nf], wb1[j][nf]);
        }

        // write this warp's partial (16 x 64)
        {
            float* P = Part + warp * (16 * PS);
#pragma unroll
            for (int nf = 0; nf < 8; ++nf) {
                int co = nf * 8 + cc;
                *(float2*)(P + rr * PS + co)       = make_float2(acc[nf][0], acc[nf][1]);
                *(float2*)(P + (rr + 8) * PS + co) = make_float2(acc[nf][2], acc[nf][3]);
            }
        }
        __syncthreads();   // partials visible CTA-wide

        // reduce 8 partials + preX, tanh, state update, publish, remote arrives
        {
            float s0 = px.x, s1 = px.y, s2 = px.z, s3 = px.w;
#pragma unroll
            for (int p = 0; p < KW; ++p) {
                float4 v = *(const float4*)(Part + p * (16 * PS) + srow * PS + scol);
                s0 += v.x; s1 += v.y; s2 += v.z; s3 += v.w;
            }
            float pre0 = fast_tanh(s0);
            float pre1 = fast_tanh(s1);
            float pre2 = fast_tanh(s2);
            float pre3 = fast_tanh(s3);
            hzr[0] += DTc * (pre0 - GAMc * hyr[0] - EPSc * hzr[0]);  hyr[0] += DTc * hzr[0];
            hzr[1] += DTc * (pre1 - GAMc * hyr[1] - EPSc * hzr[1]);  hyr[1] += DTc * hzr[1];
            hzr[2] += DTc * (pre2 - GAMc * hyr[2] - EPSc * hzr[2]);  hyr[2] += DTc * hzr[2];
            hzr[3] += DTc * (pre3 - GAMc * hyr[3] - EPSc * hzr[3]);  hyr[3] += DTc * hzr[3];

            __stcg(&g_Hz[wbuf][hbase + pos0], pack_h2(hzr[0], hzr[1]));
            __stcg(&g_Hz[wbuf][hbase + pos1], pack_h2(hzr[2], hzr[3]));
            __stcg(&g_Hy[wbuf][hbase + pos0], pack_h2(hyr[0], hyr[1]));
            __stcg(&g_Hy[wbuf][hbase + pos1], pack_h2(hyr[2], hyr[3]));
            if (t == TSTEPS - 1) {
                __stcg((float4*)&g_hyf[(size_t)grow * NHID + gcol],
                       make_float4(hyr[0], hyr[1], hyr[2], hyr[3]));
            }
        }
        __syncwarp();
        if (lane == 0) {
#pragma unroll
            for (unsigned r = 0; r < CLUSTER; ++r) mbar_arrive_rank(mbaddr, r);  // phase t+1
        }
    }

    // ---- final wait: phase TSTEPS (parity 0) — all final states of rows mi published ----
    if (lane == 0) mbar_wait(mbaddr, (unsigned)(TSTEPS & 1));
    __syncthreads();

    // ---- fused output GEMM: out = hy_final @ Wout + bout ----
    if (warp < 2) {
        int row = cta * 2 + warp;              // row belongs to this cluster's mi group
        const float* h = g_hyf + (size_t)row * NHID;
        float acc[NOUT];
#pragma unroll
        for (int o = 0; o < NOUT; ++o) acc[o] = 0.f;
        for (int k = lane; k < NHID; k += 32) {
            float hv = __ldcg(h + k);
#pragma unroll
            for (int o = 0; o < NOUT; ++o) acc[o] += hv * Wout[k * NOUT + o];
        }
#pragma unroll
        for (int o = 0; o < NOUT; ++o) {
#pragma unroll
            for (int s = 16; s > 0; s >>= 1)
                acc[o] += __shfl_xor_sync(0xffffffffu, acc[o], s);
        }
        if (lane == 0) {
#pragma unroll
            for (int o = 0; o < NOUT; ++o) out[row * NOUT + o] = acc[o] + bout[o];
        }
    }

    // no CTA may exit while peers might still target our smem mbar: all are past
    // their last arrives (they completed phase TSTEPS before our wait returned),
    // but keep a cluster barrier for strict safety on exit.
    asm volatile("barrier.cluster.arrive.aligned;" ::: "memory");
    asm volatile("barrier.cluster.wait.aligned;" ::: "memory");
}

// ---------------- launch ----------------
extern "C" void kernel_launch(void* const* d_in, const int* in_sizes, int n_in,
                              void* d_out, int out_size) {
    (void)in_sizes; (void)n_in; (void)out_size;
    const float* x    = (const float*)d_in[0];
    const float* W    = (const float*)d_in[1];
    const float* b    = (const float*)d_in[2];
    const float* Wout = (const float*)d_in[3];
    const float* bout = (const float*)d_in[4];
    float* out = (float*)d_out;

    cornn_persist<<<NCTA, THREADS>>>(x, W, b, Wout, bout, out);
}

// round 12
// speedup vs baseline: 2.1286x; 2.1286x over previous
#include <cuda_runtime.h>
#include <cuda_fp16.h>
#include <stdint.h>

// ---------------- problem constants ----------------
#define TSTEPS 512
#define BSZ    256
#define NIN    128
#define NHID   512
#define NOUT   10
#define DTc    0.042f
#define GAMc   2.7f
#define EPSc   4.7f

// ---------------- kernel config ----------------
#define NCTA    128          // 8 M-tiles(32) x 16 N-tiles(32)
#define KW      8            // warps; each = m32 x n32, k-slice of 128 (state part)
#define THREADS (KW*32)      // 256
#define JPW     8            // k16-blocks per warp
#define PS      36           // partial row stride (16B-aligned rows)

// sub-barrier: counter per (t, mi, s) on its own 256B line; 32 arrivals each
#define BARIDX(t, mi, s) (((((t) * 8) + (mi)) * 4 + (s)) * 64)
#define ARRIVALS 32u

#define PART_WORDS (KW * 32 * PS)            // 9216 per buffer
#define SMEM_BYTES (2 * PART_WORDS * 4)      // 73,728 B (double-buffered)

// ---------------- device scratch ----------------
// fp16 state, R6-proven layout: row-major [256 rows][32 blocks of 16 cols];
// within a block, col-pair p (cols 2p,2p+1) at u32 position perm(p):
//   perm(p) = p<4 ? 2p : 2(p-4)+1   -> consumer lane c LDG.64 reads pairs {c, 4+c}
__device__ unsigned g_Hz[2][BSZ*256];
__device__ unsigned g_Hy[2][BSZ*256];
__device__ float    g_preX[(size_t)NCTA*TSTEPS*32*32];  // x@Wx + bias, per-CTA patches
__device__ float    g_hyf[BSZ*NHID];                    // final hy (fp32)
__device__ unsigned g_bar[(TSTEPS+1)*8*4*64];           // padded (t,mi,s) counters
__device__ unsigned g_fin[8];                           // final per-mi CTA counters

// ---------------- helpers ----------------
__device__ __forceinline__ float fast_tanh(float v) {
    float e = __expf(2.0f * v);
    return 1.0f - __fdividef(2.0f, e + 1.0f);
}
__device__ __forceinline__ unsigned pack_h2(float lo, float hi) {
    __half2 h = __floats2half2_rn(lo, hi);
    return *reinterpret_cast<unsigned*>(&h);
}
__device__ __forceinline__ void mma_f16(float* d,
                                        unsigned a0, unsigned a1, unsigned a2, unsigned a3,
                                        unsigned b0, unsigned b1) {
    asm volatile("mma.sync.aligned.m16n8k16.row.col.f32.f16.f16.f32 "
                 "{%0,%1,%2,%3}, {%4,%5,%6,%7}, {%8,%9}, {%0,%1,%2,%3};"
                 : "+f"(d[0]), "+f"(d[1]), "+f"(d[2]), "+f"(d[3])
                 : "r"(a0), "r"(a1), "r"(a2), "r"(a3), "r"(b0), "r"(b1));
}
__device__ __forceinline__ void bar_arrive(int idx) {
    asm volatile("red.release.gpu.global.add.u32 [%0], 1;" :: "l"(&g_bar[idx]) : "memory");
}
__device__ __forceinline__ void poll_n(int idx, unsigned n) {
    unsigned v;
    do {
        asm volatile("ld.acquire.gpu.global.u32 %0, [%1];" : "=r"(v) : "l"(&g_bar[idx]) : "memory");
    } while (v < n);
}
__device__ __forceinline__ float2 ldcg2(const float* p) {
    return __ldcg(reinterpret_cast<const float2*>(p));
}

// ================= single persistent kernel =================
__global__ void __launch_bounds__(THREADS, 1)
cornn_persist(const float* __restrict__ x, const float* __restrict__ W,
              const float* __restrict__ bias,
              const float* __restrict__ Wout, const float* __restrict__ bout,
              float* __restrict__ out) {
    extern __shared__ float PartBuf[];   // [2][KW*32*PS]

    const int tid  = threadIdx.x;
    const int cta  = blockIdx.x;
    const int mi   = cta >> 4;            // 0..7
    const int ni   = cta & 15;            // 0..15
    const int lane = tid & 31;
    const int warp = tid >> 5;            // 0..7
    const int rr   = lane >> 2;
    const int cc   = 2 * (lane & 3);
    const int sp   = ni >> 2;             // producer slice group
    const int sc   = warp & 3;            // consumer slice needed

    // ================= phase 1: preX[t] = x_t @ W[0:128] + b (per-CTA patches) =================
    {
        unsigned xb0[JPW][4], xb1[JPW][4];
        const int n = ni * 32 + rr;
#pragma unroll
        for (int j = 0; j < JPW; ++j) {
            const int k0 = j * 16 + cc;
#pragma unroll
            for (int nf = 0; nf < 4; ++nf) {
                const float* wp = W + (size_t)k0 * NHID + n + nf * 8;
                xb0[j][nf] = pack_h2(wp[0],        wp[NHID]);
                xb1[j][nf] = pack_h2(wp[8 * NHID], wp[9 * NHID]);
            }
        }
        float bc[4][2];
#pragma unroll
        for (int nf = 0; nf < 4; ++nf) {
            int col = ni * 32 + nf * 8 + cc;
            bc[nf][0] = bias[col];
            bc[nf][1] = bias[col + 1];
        }
        const int arow = mi * 32 + rr;
        for (int i = 0; i < TSTEPS / KW; ++i) {
            const int t = warp + KW * i;
            float acc0[4][4], acc1[4][4];
#pragma unroll
            for (int nf = 0; nf < 4; ++nf) {
                acc0[nf][0] = bc[nf][0]; acc0[nf][1] = bc[nf][1];
                acc0[nf][2] = bc[nf][0]; acc0[nf][3] = bc[nf][1];
                acc1[nf][0] = bc[nf][0]; acc1[nf][1] = bc[nf][1];
                acc1[nf][2] = bc[nf][0]; acc1[nf][3] = bc[nf][1];
            }
            const float* rx = x + ((size_t)t * BSZ + arow) * NIN + cc;
#pragma unroll
            for (int j = 0; j < JPW; ++j) {
                float2 v0l = ldcg2(rx + j * 16),            v0h = ldcg2(rx + j * 16 + 8);
                float2 v1l = ldcg2(rx + 8 * NIN + j * 16),  v1h = ldcg2(rx + 8 * NIN + j * 16 + 8);
                float2 v2l = ldcg2(rx + 16 * NIN + j * 16), v2h = ldcg2(rx + 16 * NIN + j * 16 + 8);
                float2 v3l = ldcg2(rx + 24 * NIN + j * 16), v3h = ldcg2(rx + 24 * NIN + j * 16 + 8);
                unsigned a0l = pack_h2(v0l.x, v0l.y), a0h = pack_h2(v0h.x, v0h.y);
                unsigned a1l = pack_h2(v1l.x, v1l.y), a1h = pack_h2(v1h.x, v1h.y);
                unsigned a2l = pack_h2(v2l.x, v2l.y), a2h = pack_h2(v2h.x, v2h.y);
                unsigned a3l = pack_h2(v3l.x, v3l.y), a3h = pack_h2(v3h.x, v3h.y);
#pragma unroll
                for (int nf = 0; nf < 4; ++nf) {
                    mma_f16(acc0[nf], a0l, a1l, a0h, a1h, xb0[j][nf], xb1[j][nf]);
                    mma_f16(acc1[nf], a2l, a3l, a2h, a3h, xb0[j][nf], xb1[j][nf]);
                }
            }
            float* dst = g_preX + ((size_t)(cta * TSTEPS + t) * 32) * 32;
#pragma unroll
            for (int nf = 0; nf < 4; ++nf) {
                int co = nf * 8 + cc;
                __stcg((float2*)(dst + rr * 32 + co),        make_float2(acc0[nf][0], acc0[nf][1]));
                __stcg((float2*)(dst + (rr + 8) * 32 + co),  make_float2(acc0[nf][2], acc0[nf][3]));
                __stcg((float2*)(dst + (rr + 16) * 32 + co), make_float2(acc1[nf][0], acc1[nf][1]));
                __stcg((float2*)(dst + (rr + 24) * 32 + co), make_float2(acc1[nf][2], acc1[nf][3]));
            }
        }
    }

    // ================= init: zero fp16 state (buffer 0), per-warp arrive C[0] =================
    const int srow = tid >> 3;                 // 0..31 (warp w owns rows 4w..4w+3)
    const int scol = (tid & 7) * 4;
    const int grow = mi * 32 + srow;
    const int gcol = ni * 32 + scol;
    const int blk  = gcol >> 4;
    const int pp   = (gcol & 15) >> 1;
    const int pos0 = (pp < 4) ? 2 * pp : 2 * pp - 7;
    const int pos1 = ((pp + 1) < 4) ? 2 * (pp + 1) : 2 * (pp + 1) - 7;
    const int hbase = grow * 256 + blk * 8;

    __stcg(&g_Hz[0][hbase + pos0], 0u);  __stcg(&g_Hz[0][hbase + pos1], 0u);
    __stcg(&g_Hy[0][hbase + pos0], 0u);  __stcg(&g_Hy[0][hbase + pos1], 0u);
    __syncwarp();
    if (lane == 0) bar_arrive(BARIDX(0, mi, sp));

    // ---- main-loop B fragments: W rows 128 + warp*128 .. +128 ----
    unsigned wb0[JPW][4], wb1[JPW][4];
    {
        const int n = ni * 32 + rr;
#pragma unroll
        for (int j = 0; j < JPW; ++j) {
            const int k0 = 128 + warp * 128 + j * 16 + cc;
#pragma unroll
            for (int nf = 0; nf < 4; ++nf) {
                const float* wp = W + (size_t)k0 * NHID + n + nf * 8;
                wb0[j][nf] = pack_h2(wp[0],        wp[NHID]);
                wb1[j][nf] = pack_h2(wp[8 * NHID], wp[9 * NHID]);
            }
        }
    }

    // consumer A-fragment base (R6 layout)
    const int hoff = (mi * 32 + rr) * 256 + sc * 64 + 2 * (lane & 3);

    float hyr[4] = {0, 0, 0, 0}, hzr[4] = {0, 0, 0, 0};

    // preX prefetch one step ahead
    const float* pxbase = g_preX + ((size_t)cta * TSTEPS * 32 + srow) * 32 + scol;
    float4 px = __ldcg((const float4*)(pxbase));

    // ================= recurrence =================
    for (int t = 0; t < TSTEPS; ++t) {
        const int rb = t & 1, wbuf = rb ^ 1;

        // prefetch next step's preX patch now (full step of latency slack)
        const int tn = (t + 1 < TSTEPS) ? t + 1 : t;
        float4 px_next = __ldcg((const float4*)(pxbase + (size_t)tn * 32 * 32));

        // per-warp poll: only the 4 producer CTAs of this warp's k-slice
        if (lane == 0) poll_n(BARIDX(t, mi, sc), ARRIVALS);
        __syncwarp();

        const unsigned* hp = ((warp < 4) ? g_Hz[rb] : g_Hy[rb]) + hoff;

        float acc0[4][4], acc1[4][4];
#pragma unroll
        for (int nf = 0; nf < 4; ++nf)
#pragma unroll
            for (int c = 0; c < 4; ++c) { acc0[nf][c] = 0.f; acc1[nf][c] = 0.f; }

#pragma unroll
        for (int j = 0; j < JPW; ++j) {
            const unsigned* q = hp + j * 8;
            uint2 u0 = __ldcg((const uint2*)(q));
            uint2 u1 = __ldcg((const uint2*)(q + 8 * 256));
            uint2 u2 = __ldcg((const uint2*)(q + 16 * 256));
            uint2 u3 = __ldcg((const uint2*)(q + 24 * 256));
#pragma unroll
            for (int nf = 0; nf < 4; ++nf) {
                mma_f16(acc0[nf], u0.x, u1.x, u0.y, u1.y, wb0[j][nf], wb1[j][nf]);
                mma_f16(acc1[nf], u2.x, u3.x, u2.y, u3.y, wb0[j][nf], wb1[j][nf]);
            }
        }

        // write this warp's partial (t-parity buffer: safe under sub-barrier skew)
        float* Part = PartBuf + (t & 1) * PART_WORDS;
        {
            float* P = Part + warp * (32 * PS);
#pragma unroll
            for (int nf = 0; nf < 4; ++nf) {
                int co = nf * 8 + cc;
                *(float2*)(P + rr * PS + co)        = make_float2(acc0[nf][0], acc0[nf][1]);
                *(float2*)(P + (rr + 8) * PS + co)  = make_float2(acc0[nf][2], acc0[nf][3]);
                *(float2*)(P + (rr + 16) * PS + co) = make_float2(acc1[nf][0], acc1[nf][1]);
                *(float2*)(P + (rr + 24) * PS + co) = make_float2(acc1[nf][2], acc1[nf][3]);
            }
        }
        __syncthreads();   // single CTA-wide barrier: partials visible

        // reduce 8 partials + preX, tanh, state update, publish, per-warp arrive
        {
            float s0 = px.x, s1 = px.y, s2 = px.z, s3 = px.w;
#pragma unroll
            for (int p = 0; p < KW; ++p) {
                float4 v = *(const float4*)(Part + p * (32 * PS) + srow * PS + scol);
                s0 += v.x; s1 += v.y; s2 += v.z; s3 += v.w;
            }
            float pre0 = fast_tanh(s0);
            float pre1 = fast_tanh(s1);
            float pre2 = fast_tanh(s2);
            float pre3 = fast_tanh(s3);
            hzr[0] += DTc * (pre0 - GAMc * hyr[0] - EPSc * hzr[0]);  hyr[0] += DTc * hzr[0];
            hzr[1] += DTc * (pre1 - GAMc * hyr[1] - EPSc * hzr[1]);  hyr[1] += DTc * hzr[1];
            hzr[2] += DTc * (pre2 - GAMc * hyr[2] - EPSc * hzr[2]);  hyr[2] += DTc * hzr[2];
            hzr[3] += DTc * (pre3 - GAMc * hyr[3] - EPSc * hzr[3]);  hyr[3] += DTc * hzr[3];

            __stcg(&g_Hz[wbuf][hbase + pos0], pack_h2(hzr[0], hzr[1]));
            __stcg(&g_Hz[wbuf][hbase + pos1], pack_h2(hzr[2], hzr[3]));
            __stcg(&g_Hy[wbuf][hbase + pos0], pack_h2(hyr[0], hyr[1]));
            __stcg(&g_Hy[wbuf][hbase + pos1], pack_h2(hyr[2], hyr[3]));
            if (t == TSTEPS - 1) {
                __stcg((float4*)&g_hyf[(size_t)grow * NHID + gcol],
                       make_float4(hyr[0], hyr[1], hyr[2], hyr[3]));
            }
        }
        __syncwarp();
        if (lane == 0) bar_arrive(BARIDX(t + 1, mi, sp));   // this warp's rows published
        px = px_next;
    }

    // ---- final wait: all 4 slice counters of step TSTEPS (whole mi group done) ----
    if (tid == 0) {
#pragma unroll
        for (int s = 0; s < 4; ++s) poll_n(BARIDX(TSTEPS, mi, s), ARRIVALS);
    }
    __syncthreads();

    // ---- fused output GEMM: out = hy_final @ Wout + bout ----
    if (warp < 2) {
        int row = cta * 2 + warp;              // row in this CTA's mi group
        const float* h = g_hyf + (size_t)row * NHID;
        float acc[NOUT];
#pragma unroll
        for (int o = 0; o < NOUT; ++o) acc[o] = 0.f;
        for (int k = lane; k < NHID; k += 32) {
            float hv = __ldcg(h + k);
#pragma unroll
            for (int o = 0; o < NOUT; ++o) acc[o] += hv * Wout[k * NOUT + o];
        }
#pragma unroll
        for (int o = 0; o < NOUT; ++o) {
#pragma unroll
            for (int s = 16; s > 0; s >>= 1)
                acc[o] += __shfl_xor_sync(0xffffffffu, acc[o], s);
        }
        if (lane == 0) {
#pragma unroll
            for (int o = 0; o < NOUT; ++o) out[row * NOUT + o] = acc[o] + bout[o];
        }
    }

    // ---- safe self-reset: last CTA of mi group (all pollers of mi already done) ----
    __shared__ unsigned s_last;
    if (tid == 0) {
        unsigned old = atomicAdd(&g_fin[mi], 1u);
        s_last = (old == 15u) ? 1u : 0u;
    }
    __syncthreads();
    if (s_last) {
        for (int i = tid; i < (TSTEPS + 1) * 4; i += THREADS) {
            int tt = i >> 2, s = i & 3;
            g_bar[BARIDX(tt, mi, s)] = 0u;
        }
        __syncthreads();
        if (tid == 0) {
            __threadfence();
            g_fin[mi] = 0u;
        }
    }
}

// ---------------- launch ----------------
extern "C" void kernel_launch(void* const* d_in, const int* in_sizes, int n_in,
                              void* d_out, int out_size) {
    (void)in_sizes; (void)n_in; (void)out_size;
    const float* x    = (const float*)d_in[0];
    const float* W    = (const float*)d_in[1];
    const float* b    = (const float*)d_in[2];
    const float* Wout = (const float*)d_in[3];
    const float* bout = (const float*)d_in[4];
    float* out = (float*)d_out;

    cudaFuncSetAttribute(cornn_persist, cudaFuncAttributeMaxDynamicSharedMemorySize, SMEM_BYTES);
    cornn_persist<<<NCTA, THREADS, SMEM_BYTES>>>(x, W, b, Wout, bout, out);
}

// round 13
// speedup vs baseline: 2.4255x; 1.1395x over previous
#include <cuda_runtime.h>
#include <cuda_fp16.h>
#include <stdint.h>

// ---------------- problem constants ----------------
#define TSTEPS 512
#define BSZ    256
#define NIN    128
#define NHID   512
#define NOUT   10
#define DTc    0.042f
#define GAMc   2.7f
#define EPSc   4.7f

// ---------------- kernel config ----------------
#define NCTA    128          // 8 M-tiles(32) x 16 N-tiles(32)
#define KW      8            // warps; each = m32 x n32, k-slice of 128 (state part)
#define THREADS (KW*32)      // 256
#define JPW     8            // k16-blocks per warp
#define PS      36           // partial row stride (16B-aligned rows)

// counter per (t, mi) on its own 256B line; 128 per-warp arrivals each
#define BARIDX(t, mi) ((((t) * 8) + (mi)) * 64)
#define ARRIVALS 128u

// ---------------- device scratch ----------------
// fp16 state, warp-contiguous fragment layout:
//   g_H[buf][ (mi*4+slice)*8 + j ][ row(32) ][ pl(4) ][ ph(2) ]   (u32 = half2)
// pair p (cols 2p,2p+1 of k16-block j) stored at (pl = p&3, ph = p>>2).
// Consumer lane (rr, c) reads uint2 at row*8 + c*2 = {pair c (kh1), pair c+4 (kh2)}
// -> 32 lanes of one LDG.64 span 256B contiguous = 2 L1 wavefronts (was 8).
__device__ unsigned g_Hz[2][8*4*8*32*8];               // 65536 u32 per buffer
__device__ unsigned g_Hy[2][8*4*8*32*8];
__device__ float    g_preX[(size_t)NCTA*TSTEPS*32*32]; // x@Wx + bias, per-CTA patches
__device__ float    g_hyf[BSZ*NHID];                   // final hy (fp32)
__device__ unsigned g_bar[(TSTEPS+1)*8*64];            // padded (t,mi) counters
__device__ unsigned g_fin[8];                          // final per-mi CTA counters

// ---------------- helpers ----------------
__device__ __forceinline__ float fast_tanh(float v) {
    float e = __expf(2.0f * v);
    return 1.0f - __fdividef(2.0f, e + 1.0f);
}
__device__ __forceinline__ unsigned pack_h2(float lo, float hi) {
    __half2 h = __floats2half2_rn(lo, hi);
    return *reinterpret_cast<unsigned*>(&h);
}
__device__ __forceinline__ void mma_f16(float* d,
                                        unsigned a0, unsigned a1, unsigned a2, unsigned a3,
                                        unsigned b0, unsigned b1) {
    asm volatile("mma.sync.aligned.m16n8k16.row.col.f32.f16.f16.f32 "
                 "{%0,%1,%2,%3}, {%4,%5,%6,%7}, {%8,%9}, {%0,%1,%2,%3};"
                 : "+f"(d[0]), "+f"(d[1]), "+f"(d[2]), "+f"(d[3])
                 : "r"(a0), "r"(a1), "r"(a2), "r"(a3), "r"(b0), "r"(b1));
}
__device__ __forceinline__ void bar_arrive(int idx) {
    asm volatile("red.release.gpu.global.add.u32 [%0], 1;" :: "l"(&g_bar[idx]) : "memory");
}
__device__ __forceinline__ void poll_n(int idx, unsigned n) {
    unsigned v;
    do {
        asm volatile("ld.acquire.gpu.global.u32 %0, [%1];" : "=r"(v) : "l"(&g_bar[idx]) : "memory");
    } while (v < n);
}
__device__ __forceinline__ float2 ldcg2(const float* p) {
    return __ldcg(reinterpret_cast<const float2*>(p));
}

// ================= single persistent kernel =================
__global__ void __launch_bounds__(THREADS, 1)
cornn_persist(const float* __restrict__ x, const float* __restrict__ W,
              const float* __restrict__ bias,
              const float* __restrict__ Wout, const float* __restrict__ bout,
              float* __restrict__ out) {
    __shared__ float Part[KW * 32 * PS];

    const int tid  = threadIdx.x;
    const int cta  = blockIdx.x;
    const int mi   = cta >> 4;            // 0..7
    const int ni   = cta & 15;            // 0..15
    const int lane = tid & 31;
    const int warp = tid >> 5;            // 0..7
    const int rr   = lane >> 2;
    const int cc   = 2 * (lane & 3);

    // ================= phase 1: preX[t] = x_t @ W[0:128] + b (per-CTA patches) =================
    {
        unsigned xb0[JPW][4], xb1[JPW][4];
        const int n = ni * 32 + rr;
#pragma unroll
        for (int j = 0; j < JPW; ++j) {
            const int k0 = j * 16 + cc;
#pragma unroll
            for (int nf = 0; nf < 4; ++nf) {
                const float* wp = W + (size_t)k0 * NHID + n + nf * 8;
                xb0[j][nf] = pack_h2(wp[0],        wp[NHID]);
                xb1[j][nf] = pack_h2(wp[8 * NHID], wp[9 * NHID]);
            }
        }
        float bc[4][2];
#pragma unroll
        for (int nf = 0; nf < 4; ++nf) {
            int col = ni * 32 + nf * 8 + cc;
            bc[nf][0] = bias[col];
            bc[nf][1] = bias[col + 1];
        }
        const int arow = mi * 32 + rr;
        for (int i = 0; i < TSTEPS / KW; ++i) {
            const int t = warp + KW * i;
            float acc0[4][4], acc1[4][4];
#pragma unroll
            for (int nf = 0; nf < 4; ++nf) {
                acc0[nf][0] = bc[nf][0]; acc0[nf][1] = bc[nf][1];
                acc0[nf][2] = bc[nf][0]; acc0[nf][3] = bc[nf][1];
                acc1[nf][0] = bc[nf][0]; acc1[nf][1] = bc[nf][1];
                acc1[nf][2] = bc[nf][0]; acc1[nf][3] = bc[nf][1];
            }
            const float* rx = x + ((size_t)t * BSZ + arow) * NIN + cc;
#pragma unroll
            for (int j = 0; j < JPW; ++j) {
                float2 v0l = ldcg2(rx + j * 16),            v0h = ldcg2(rx + j * 16 + 8);
                float2 v1l = ldcg2(rx + 8 * NIN + j * 16),  v1h = ldcg2(rx + 8 * NIN + j * 16 + 8);
                float2 v2l = ldcg2(rx + 16 * NIN + j * 16), v2h = ldcg2(rx + 16 * NIN + j * 16 + 8);
                float2 v3l = ldcg2(rx + 24 * NIN + j * 16), v3h = ldcg2(rx + 24 * NIN + j * 16 + 8);
                unsigned a0l = pack_h2(v0l.x, v0l.y), a0h = pack_h2(v0h.x, v0h.y);
                unsigned a1l = pack_h2(v1l.x, v1l.y), a1h = pack_h2(v1h.x, v1h.y);
                unsigned a2l = pack_h2(v2l.x, v2l.y), a2h = pack_h2(v2h.x, v2h.y);
                unsigned a3l = pack_h2(v3l.x, v3l.y), a3h = pack_h2(v3h.x, v3h.y);
#pragma unroll
                for (int nf = 0; nf < 4; ++nf) {
                    mma_f16(acc0[nf], a0l, a1l, a0h, a1h, xb0[j][nf], xb1[j][nf]);
                    mma_f16(acc1[nf], a2l, a3l, a2h, a3h, xb0[j][nf], xb1[j][nf]);
                }
            }
            float* dst = g_preX + ((size_t)(cta * TSTEPS + t) * 32) * 32;
#pragma unroll
            for (int nf = 0; nf < 4; ++nf) {
                int co = nf * 8 + cc;
                __stcg((float2*)(dst + rr * 32 + co),        make_float2(acc0[nf][0], acc0[nf][1]));
                __stcg((float2*)(dst + (rr + 8) * 32 + co),  make_float2(acc0[nf][2], acc0[nf][3]));
                __stcg((float2*)(dst + (rr + 16) * 32 + co), make_float2(acc1[nf][0], acc1[nf][1]));
                __stcg((float2*)(dst + (rr + 24) * 32 + co), make_float2(acc1[nf][2], acc1[nf][3]));
            }
        }
    }

    // ================= producer store addresses (new layout) =================
    const int srow = tid >> 3;                 // 0..31 (warp w owns rows 4w..4w+3)
    const int scol = (tid & 7) * 4;            // 0,4,..,28
    const int grow = mi * 32 + srow;
    const int gcol = ni * 32 + scol;
    const int sl   = gcol >> 7;                // slice 0..3
    const int lc   = gcol & 127;
    const int jj   = lc >> 4;                  // k16-block within slice
    const int p0   = (lc & 15) >> 1;           // even pair index 0,2,4,6
    const int pl0  = p0 & 3;
    const int ph0  = p0 >> 2;
    const int hb   = ((mi * 4 + sl) * 8 + jj) * 256 + srow * 8;
    const int a0i  = hb + pl0 * 2 + ph0;
    const int a1i  = hb + (pl0 + 1) * 2 + ph0;

    // zero initial state (buffer 0), per-warp arrive (t=0)
    __stcg(&g_Hz[0][a0i], 0u);  __stcg(&g_Hz[0][a1i], 0u);
    __stcg(&g_Hy[0][a0i], 0u);  __stcg(&g_Hy[0][a1i], 0u);
    __syncwarp();
    if (lane == 0) bar_arrive(BARIDX(0, mi));

    // ---- main-loop B fragments: W rows 128 + warp*128 .. +128 ----
    unsigned wb0[JPW][4], wb1[JPW][4];
    {
        const int n = ni * 32 + rr;
#pragma unroll
        for (int j = 0; j < JPW; ++j) {
            const int k0 = 128 + warp * 128 + j * 16 + cc;
#pragma unroll
            for (int nf = 0; nf < 4; ++nf) {
                const float* wp = W + (size_t)k0 * NHID + n + nf * 8;
                wb0[j][nf] = pack_h2(wp[0],        wp[NHID]);
                wb1[j][nf] = pack_h2(wp[8 * NHID], wp[9 * NHID]);
            }
        }
    }

    // consumer A-fragment base (new layout): slice = warp&3, lane offset rr*8 + c*2
    const int hoff = (mi * 4 + (warp & 3)) * 2048 + rr * 8 + cc;

    float hyr[4] = {0, 0, 0, 0}, hzr[4] = {0, 0, 0, 0};

    // preX prefetch one step ahead
    const float* pxbase = g_preX + ((size_t)cta * TSTEPS * 32 + srow) * 32 + scol;
    float4 px = __ldcg((const float4*)(pxbase));

    // ================= recurrence =================
    for (int t = 0; t < TSTEPS; ++t) {
        const int rb = t & 1, wbuf = rb ^ 1;

        // prefetch next step's preX patch (full step of latency slack)
        const int tn = (t + 1 < TSTEPS) ? t + 1 : t;
        float4 px_next = __ldcg((const float4*)(pxbase + (size_t)tn * 32 * 32));

        // per-warp poll: all 128 producer-warps of this mi group published step t
        if (lane == 0) poll_n(BARIDX(t, mi), ARRIVALS);
        __syncwarp();

        const unsigned* hp = ((warp < 4) ? g_Hz[rb] : g_Hy[rb]) + hoff;

        float acc0[4][4], acc1[4][4];
#pragma unroll
        for (int nf = 0; nf < 4; ++nf)
#pragma unroll
            for (int c = 0; c < 4; ++c) { acc0[nf][c] = 0.f; acc1[nf][c] = 0.f; }

#pragma unroll
        for (int j = 0; j < JPW; ++j) {
            const unsigned* q = hp + j * 256;     // block j; rows +8 -> +64 u32
            uint2 u0 = __ldcg((const uint2*)(q));
            uint2 u1 = __ldcg((const uint2*)(q + 64));
            uint2 u2 = __ldcg((const uint2*)(q + 128));
            uint2 u3 = __ldcg((const uint2*)(q + 192));
#pragma unroll
            for (int nf = 0; nf < 4; ++nf) {
                mma_f16(acc0[nf], u0.x, u1.x, u0.y, u1.y, wb0[j][nf], wb1[j][nf]);
                mma_f16(acc1[nf], u2.x, u3.x, u2.y, u3.y, wb0[j][nf], wb1[j][nf]);
            }
        }

        // write this warp's partial
        {
            float* P = Part + warp * (32 * PS);
#pragma unroll
            for (int nf = 0; nf < 4; ++nf) {
                int co = nf * 8 + cc;
                *(float2*)(P + rr * PS + co)        = make_float2(acc0[nf][0], acc0[nf][1]);
                *(float2*)(P + (rr + 8) * PS + co)  = make_float2(acc0[nf][2], acc0[nf][3]);
                *(float2*)(P + (rr + 16) * PS + co) = make_float2(acc1[nf][0], acc1[nf][1]);
                *(float2*)(P + (rr + 24) * PS + co) = make_float2(acc1[nf][2], acc1[nf][3]);
            }
        }
        __syncthreads();   // single CTA-wide barrier: partials visible

        // reduce 8 partials + preX, tanh, state update, publish, per-warp arrive
        {
            float s0 = px.x, s1 = px.y, s2 = px.z, s3 = px.w;
#pragma unroll
            for (int p = 0; p < KW; ++p) {
                float4 v = *(const float4*)(Part + p * (32 * PS) + srow * PS + scol);
                s0 += v.x; s1 += v.y; s2 += v.z; s3 += v.w;
            }
            float pre0 = fast_tanh(s0);
            float pre1 = fast_tanh(s1);
            float pre2 = fast_tanh(s2);
            float pre3 = fast_tanh(s3);
            hzr[0] += DTc * (pre0 - GAMc * hyr[0] - EPSc * hzr[0]);  hyr[0] += DTc * hzr[0];
            hzr[1] += DTc * (pre1 - GAMc * hyr[1] - EPSc * hzr[1]);  hyr[1] += DTc * hzr[1];
            hzr[2] += DTc * (pre2 - GAMc * hyr[2] - EPSc * hzr[2]);  hyr[2] += DTc * hzr[2];
            hzr[3] += DTc * (pre3 - GAMc * hyr[3] - EPSc * hzr[3]);  hyr[3] += DTc * hzr[3];

            __stcg(&g_Hz[wbuf][a0i], pack_h2(hzr[0], hzr[1]));
            __stcg(&g_Hz[wbuf][a1i], pack_h2(hzr[2], hzr[3]));
            __stcg(&g_Hy[wbuf][a0i], pack_h2(hyr[0], hyr[1]));
            __stcg(&g_Hy[wbuf][a1i], pack_h2(hyr[2], hyr[3]));
            if (t == TSTEPS - 1) {
                __stcg((float4*)&g_hyf[(size_t)grow * NHID + gcol],
                       make_float4(hyr[0], hyr[1], hyr[2], hyr[3]));
            }
        }
        __syncwarp();
        if (lane == 0) bar_arrive(BARIDX(t + 1, mi));   // this warp's rows published
        px = px_next;
    }

    // ---- final wait: all 128 producer-warps of rows mi done ----
    if (tid == 0) poll_n(BARIDX(TSTEPS, mi), ARRIVALS);
    __syncthreads();

    // ---- fused output GEMM: out = hy_final @ Wout + bout ----
    if (warp < 2) {
        int row = cta * 2 + warp;
        const float* h = g_hyf + (size_t)row * NHID;
        float acc[NOUT];
#pragma unroll
        for (int o = 0; o < NOUT; ++o) acc[o] = 0.f;
        for (int k = lane; k < NHID; k += 32) {
            float hv = __ldcg(h + k);
#pragma unroll
            for (int o = 0; o < NOUT; ++o) acc[o] += hv * Wout[k * NOUT + o];
        }
#pragma unroll
        for (int o = 0; o < NOUT; ++o) {
#pragma unroll
            for (int s = 16; s > 0; s >>= 1)
                acc[o] += __shfl_xor_sync(0xffffffffu, acc[o], s);
        }
        if (lane == 0) {
#pragma unroll
            for (int o = 0; o < NOUT; ++o) out[row * NOUT + o] = acc[o] + bout[o];
        }
    }

    // ---- safe self-reset: last CTA of mi group (all pollers of mi already done) ----
    __shared__ unsigned s_last;
    if (tid == 0) {
        unsigned old = atomicAdd(&g_fin[mi], 1u);
        s_last = (old == 15u) ? 1u : 0u;
    }
    __syncthreads();
    if (s_last) {
        for (int tt = tid; tt <= TSTEPS; tt += THREADS)
            g_bar[BARIDX(tt, mi)] = 0u;
        __syncthreads();
        if (tid == 0) {
            __threadfence();
            g_fin[mi] = 0u;
        }
    }
}

// ---------------- launch ----------------
extern "C" void kernel_launch(void* const* d_in, const int* in_sizes, int n_in,
                              void* d_out, int out_size) {
    (void)in_sizes; (void)n_in; (void)out_size;
    const float* x    = (const float*)d_in[0];
    const float* W    = (const float*)d_in[1];
    const float* b    = (const float*)d_in[2];
    const float* Wout = (const float*)d_in[3];
    const float* bout = (const float*)d_in[4];
    float* out = (float*)d_out;

    cornn_persist<<<NCTA, THREADS>>>(x, W, b, Wout, bout, out);
}

// round 14
// speedup vs baseline: 2.5685x; 1.0589x over previous
#include <cuda_runtime.h>
#include <cuda_fp16.h>
#include <stdint.h>

// ---------------- problem constants ----------------
#define TSTEPS 512
#define BSZ    256
#define NIN    128
#define NHID   512
#define NOUT   10
#define DTc    0.042f
#define GAMc   2.7f
#define EPSc   4.7f

// ---------------- kernel config ----------------
#define NCTA    128          // 8 M-tiles(32) x 16 N-tiles(32)
#define KW      8            // warps; each = m32 x n32, k-slice of 128 (state part)
#define THREADS (KW*32)      // 256
#define JPW     8            // k16-blocks per warp
#define PS      40           // partial row stride (rr*8 bank pattern; 16B-aligned)

// counter per (t, mi) on its own 256B line; 128 per-warp arrivals each
#define BARIDX(t, mi) ((((t) * 8) + (mi)) * 64)
#define ARRIVALS 128u

// ---------------- device scratch ----------------
// fp16 state, block-pair-interleaved fragment layout:
//   g_H[buf][ ((mi*4+slice)*4 + m) ][ row(32) ][ 16 u32 ]
// pair p of k16-block j (j = 2m + j1) stored at pos(p,j1) = (p&3)*4 + (p>>2)*2 + j1.
// Consumer lane (rr, c): uint4 at row*16 + c*4 = {pair c(j0), pair c(j1),
// pair c+4(j0), pair c+4(j1)} -> one LDG.128 feeds TWO mma k-steps; a warp-load
// spans 512B contiguous (4 wavefronts). 16 LDG.128/warp/step (was 32 LDG.64).
__device__ unsigned g_Hz[2][8*4*4*32*16];              // 65536 u32 per buffer
__device__ unsigned g_Hy[2][8*4*4*32*16];
__device__ float    g_preX[(size_t)NCTA*TSTEPS*32*32]; // x@Wx + bias, per-CTA patches
__device__ float    g_hyf[BSZ*NHID];                   // final hy (fp32)
__device__ unsigned g_bar[(TSTEPS+1)*8*64];            // padded (t,mi) counters
__device__ unsigned g_fin[8];                          // final per-mi CTA counters

// ---------------- helpers ----------------
__device__ __forceinline__ float fast_tanh(float v) {
    float e = __expf(2.0f * v);
    return 1.0f - __fdividef(2.0f, e + 1.0f);
}
__device__ __forceinline__ unsigned pack_h2(float lo, float hi) {
    __half2 h = __floats2half2_rn(lo, hi);
    return *reinterpret_cast<unsigned*>(&h);
}
__device__ __forceinline__ void mma_f16(float* d,
                                        unsigned a0, unsigned a1, unsigned a2, unsigned a3,
                                        unsigned b0, unsigned b1) {
    asm volatile("mma.sync.aligned.m16n8k16.row.col.f32.f16.f16.f32 "
                 "{%0,%1,%2,%3}, {%4,%5,%6,%7}, {%8,%9}, {%0,%1,%2,%3};"
                 : "+f"(d[0]), "+f"(d[1]), "+f"(d[2]), "+f"(d[3])
                 : "r"(a0), "r"(a1), "r"(a2), "r"(a3), "r"(b0), "r"(b1));
}
__device__ __forceinline__ void bar_arrive(int idx) {
    asm volatile("red.release.gpu.global.add.u32 [%0], 1;" :: "l"(&g_bar[idx]) : "memory");
}
__device__ __forceinline__ void poll_n(int idx, unsigned n) {
    unsigned v;
    do {
        asm volatile("ld.acquire.gpu.global.u32 %0, [%1];" : "=r"(v) : "l"(&g_bar[idx]) : "memory");
    } while (v < n);
}
__device__ __forceinline__ float2 ldcg2(const float* p) {
    return __ldcg(reinterpret_cast<const float2*>(p));
}
__device__ __forceinline__ int pos_of(int p, int j1) {
    return (p & 3) * 4 + (p >> 2) * 2 + j1;
}

// ================= single persistent kernel =================
__global__ void __launch_bounds__(THREADS, 1)
cornn_persist(const float* __restrict__ x, const float* __restrict__ W,
              const float* __restrict__ bias,
              const float* __restrict__ Wout, const float* __restrict__ bout,
              float* __restrict__ out) {
    __shared__ float Part[KW * 32 * PS];

    const int tid  = threadIdx.x;
    const int cta  = blockIdx.x;
    const int mi   = cta >> 4;            // 0..7
    const int ni   = cta & 15;            // 0..15
    const int lane = tid & 31;
    const int warp = tid >> 5;            // 0..7
    const int rr   = lane >> 2;
    const int cc   = 2 * (lane & 3);

    // ================= phase 1: preX[t] = x_t @ W[0:128] + b (per-CTA patches) =================
    {
        unsigned xb0[JPW][4], xb1[JPW][4];
        const int n = ni * 32 + rr;
#pragma unroll
        for (int j = 0; j < JPW; ++j) {
            const int k0 = j * 16 + cc;
#pragma unroll
            for (int nf = 0; nf < 4; ++nf) {
                const float* wp = W + (size_t)k0 * NHID + n + nf * 8;
                xb0[j][nf] = pack_h2(wp[0],        wp[NHID]);
                xb1[j][nf] = pack_h2(wp[8 * NHID], wp[9 * NHID]);
            }
        }
        float bc[4][2];
#pragma unroll
        for (int nf = 0; nf < 4; ++nf) {
            int col = ni * 32 + nf * 8 + cc;
            bc[nf][0] = bias[col];
            bc[nf][1] = bias[col + 1];
        }
        const int arow = mi * 32 + rr;
        for (int i = 0; i < TSTEPS / KW; ++i) {
            const int t = warp + KW * i;
            float acc0[4][4], acc1[4][4];
#pragma unroll
            for (int nf = 0; nf < 4; ++nf) {
                acc0[nf][0] = bc[nf][0]; acc0[nf][1] = bc[nf][1];
                acc0[nf][2] = bc[nf][0]; acc0[nf][3] = bc[nf][1];
                acc1[nf][0] = bc[nf][0]; acc1[nf][1] = bc[nf][1];
                acc1[nf][2] = bc[nf][0]; acc1[nf][3] = bc[nf][1];
            }
            const float* rx = x + ((size_t)t * BSZ + arow) * NIN + cc;
#pragma unroll
            for (int j = 0; j < JPW; ++j) {
                float2 v0l = ldcg2(rx + j * 16),            v0h = ldcg2(rx + j * 16 + 8);
                float2 v1l = ldcg2(rx + 8 * NIN + j * 16),  v1h = ldcg2(rx + 8 * NIN + j * 16 + 8);
                float2 v2l = ldcg2(rx + 16 * NIN + j * 16), v2h = ldcg2(rx + 16 * NIN + j * 16 + 8);
                float2 v3l = ldcg2(rx + 24 * NIN + j * 16), v3h = ldcg2(rx + 24 * NIN + j * 16 + 8);
                unsigned a0l = pack_h2(v0l.x, v0l.y), a0h = pack_h2(v0h.x, v0h.y);
                unsigned a1l = pack_h2(v1l.x, v1l.y), a1h = pack_h2(v1h.x, v1h.y);
                unsigned a2l = pack_h2(v2l.x, v2l.y), a2h = pack_h2(v2h.x, v2h.y);
                unsigned a3l = pack_h2(v3l.x, v3l.y), a3h = pack_h2(v3h.x, v3h.y);
#pragma unroll
                for (int nf = 0; nf < 4; ++nf) {
                    mma_f16(acc0[nf], a0l, a1l, a0h, a1h, xb0[j][nf], xb1[j][nf]);
                    mma_f16(acc1[nf], a2l, a3l, a2h, a3h, xb0[j][nf], xb1[j][nf]);
                }
            }
            float* dst = g_preX + ((size_t)(cta * TSTEPS + t) * 32) * 32;
#pragma unroll
            for (int nf = 0; nf < 4; ++nf) {
                int co = nf * 8 + cc;
                __stcg((float2*)(dst + rr * 32 + co),        make_float2(acc0[nf][0], acc0[nf][1]));
                __stcg((float2*)(dst + (rr + 8) * 32 + co),  make_float2(acc0[nf][2], acc0[nf][3]));
                __stcg((float2*)(dst + (rr + 16) * 32 + co), make_float2(acc1[nf][0], acc1[nf][1]));
                __stcg((float2*)(dst + (rr + 24) * 32 + co), make_float2(acc1[nf][2], acc1[nf][3]));
            }
        }
    }

    // ================= producer store addresses (block-pair layout) =================
    const int srow = tid >> 3;                 // 0..31 (warp w owns rows 4w..4w+3)
    const int scol = (tid & 7) * 4;            // 0,4,..,28
    const int grow = mi * 32 + srow;
    const int gcol = ni * 32 + scol;
    const int sl   = gcol >> 7;                // slice 0..3
    const int lc   = gcol & 127;
    const int jj   = lc >> 4;                  // k16-block within slice
    const int m0   = jj >> 1;                  // block-pair
    const int j1   = jj & 1;
    const int p0   = (lc & 15) >> 1;           // even pair index 0,2,4,6
    const int hb   = (((mi * 4 + sl) * 4 + m0) * 32 + srow) * 16;
    const int a0i  = hb + pos_of(p0, j1);
    const int a1i  = hb + pos_of(p0 + 1, j1);

    // zero initial state (buffer 0), per-warp arrive (t=0)
    __stcg(&g_Hz[0][a0i], 0u);  __stcg(&g_Hz[0][a1i], 0u);
    __stcg(&g_Hy[0][a0i], 0u);  __stcg(&g_Hy[0][a1i], 0u);
    __syncwarp();
    if (lane == 0) bar_arrive(BARIDX(0, mi));

    // ---- main-loop B fragments: W rows 128 + warp*128 .. +128 ----
    unsigned wb0[JPW][4], wb1[JPW][4];
    {
        const int n = ni * 32 + rr;
#pragma unroll
        for (int j = 0; j < JPW; ++j) {
            const int k0 = 128 + warp * 128 + j * 16 + cc;
#pragma unroll
            for (int nf = 0; nf < 4; ++nf) {
                const float* wp = W + (size_t)k0 * NHID + n + nf * 8;
                wb0[j][nf] = pack_h2(wp[0],        wp[NHID]);
                wb1[j][nf] = pack_h2(wp[8 * NHID], wp[9 * NHID]);
            }
        }
    }

    // consumer A-fragment base: slice = warp&3; lane uint4 at row*16 + c*4
    const int hoff = (mi * 4 + (warp & 3)) * 2048 + rr * 16 + (lane & 3) * 4;

    float hyr[4] = {0, 0, 0, 0}, hzr[4] = {0, 0, 0, 0};

    // preX prefetch one step ahead
    const float* pxbase = g_preX + ((size_t)cta * TSTEPS * 32 + srow) * 32 + scol;
    float4 px = __ldcg((const float4*)(pxbase));

    // ================= recurrence =================
    for (int t = 0; t < TSTEPS; ++t) {
        const int rb = t & 1, wbuf = rb ^ 1;

        // prefetch next step's preX patch (full step of latency slack)
        const int tn = (t + 1 < TSTEPS) ? t + 1 : t;
        float4 px_next = __ldcg((const float4*)(pxbase + (size_t)tn * 32 * 32));

        // per-warp poll: all 128 producer-warps of this mi group published step t
        if (lane == 0) poll_n(BARIDX(t, mi), ARRIVALS);
        __syncwarp();

        const unsigned* hp = ((warp < 4) ? g_Hz[rb] : g_Hy[rb]) + hoff;

        float acc0[4][4], acc1[4][4];
#pragma unroll
        for (int nf = 0; nf < 4; ++nf)
#pragma unroll
            for (int c = 0; c < 4; ++c) { acc0[nf][c] = 0.f; acc1[nf][c] = 0.f; }

#pragma unroll
        for (int m = 0; m < 4; ++m) {
            const unsigned* q = hp + m * 512;     // block-pair m; rows +8 -> +128 u32
            uint4 u0 = __ldcg((const uint4*)(q));
            uint4 u1 = __ldcg((const uint4*)(q + 128));
            uint4 u2 = __ldcg((const uint4*)(q + 256));
            uint4 u3 = __ldcg((const uint4*)(q + 384));
            // block j = 2m  (even): components .x (pair c), .z (pair c+4)
#pragma unroll
            for (int nf = 0; nf < 4; ++nf) {
                mma_f16(acc0[nf], u0.x, u1.x, u0.z, u1.z, wb0[2*m][nf], wb1[2*m][nf]);
                mma_f16(acc1[nf], u2.x, u3.x, u2.z, u3.z, wb0[2*m][nf], wb1[2*m][nf]);
            }
            // block j = 2m+1 (odd): components .y, .w
#pragma unroll
            for (int nf = 0; nf < 4; ++nf) {
                mma_f16(acc0[nf], u0.y, u1.y, u0.w, u1.w, wb0[2*m+1][nf], wb1[2*m+1][nf]);
                mma_f16(acc1[nf], u2.y, u3.y, u2.w, u3.w, wb0[2*m+1][nf], wb1[2*m+1][nf]);
            }
        }

        // write this warp's partial
        {
            float* P = Part + warp * (32 * PS);
#pragma unroll
            for (int nf = 0; nf < 4; ++nf) {
                int co = nf * 8 + cc;
                *(float2*)(P + rr * PS + co)        = make_float2(acc0[nf][0], acc0[nf][1]);
                *(float2*)(P + (rr + 8) * PS + co)  = make_float2(acc0[nf][2], acc0[nf][3]);
                *(float2*)(P + (rr + 16) * PS + co) = make_float2(acc1[nf][0], acc1[nf][1]);
                *(float2*)(P + (rr + 24) * PS + co) = make_float2(acc1[nf][2], acc1[nf][3]);
            }
        }
        __syncthreads();   // single CTA-wide barrier: partials visible

        // reduce 8 partials + preX, tanh, state update, publish, per-warp arrive
        {
            float s0 = px.x, s1 = px.y, s2 = px.z, s3 = px.w;
#pragma unroll
            for (int p = 0; p < KW; ++p) {
                float4 v = *(const float4*)(Part + p * (32 * PS) + srow * PS + scol);
                s0 += v.x; s1 += v.y; s2 += v.z; s3 += v.w;
            }
            float pre0 = fast_tanh(s0);
            float pre1 = fast_tanh(s1);
            float pre2 = fast_tanh(s2);
            float pre3 = fast_tanh(s3);
            hzr[0] += DTc * (pre0 - GAMc * hyr[0] - EPSc * hzr[0]);  hyr[0] += DTc * hzr[0];
            hzr[1] += DTc * (pre1 - GAMc * hyr[1] - EPSc * hzr[1]);  hyr[1] += DTc * hzr[1];
            hzr[2] += DTc * (pre2 - GAMc * hyr[2] - EPSc * hzr[2]);  hyr[2] += DTc * hzr[2];
            hzr[3] += DTc * (pre3 - GAMc * hyr[3] - EPSc * hzr[3]);  hyr[3] += DTc * hzr[3];

            __stcg(&g_Hz[wbuf][a0i], pack_h2(hzr[0], hzr[1]));
            __stcg(&g_Hz[wbuf][a1i], pack_h2(hzr[2], hzr[3]));
            __stcg(&g_Hy[wbuf][a0i], pack_h2(hyr[0], hyr[1]));
            __stcg(&g_Hy[wbuf][a1i], pack_h2(hyr[2], hyr[3]));
            if (t == TSTEPS - 1) {
                __stcg((float4*)&g_hyf[(size_t)grow * NHID + gcol],
                       make_float4(hyr[0], hyr[1], hyr[2], hyr[3]));
            }
        }
        __syncwarp();
        if (lane == 0) bar_arrive(BARIDX(t + 1, mi));   // this warp's rows published
        px = px_next;
    }

    // ---- final wait: all 128 producer-warps of rows mi done ----
    if (tid == 0) poll_n(BARIDX(TSTEPS, mi), ARRIVALS);
    __syncthreads();

    // ---- fused output GEMM: out = hy_final @ Wout + bout ----
    if (warp < 2) {
        int row = cta * 2 + warp;
        const float* h = g_hyf + (size_t)row * NHID;
        float acc[NOUT];
#pragma unroll
        for (int o = 0; o < NOUT; ++o) acc[o] = 0.f;
        for (int k = lane; k < NHID; k += 32) {
            float hv = __ldcg(h + k);
#pragma unroll
            for (int o = 0; o < NOUT; ++o) acc[o] += hv * Wout[k * NOUT + o];
        }
#pragma unroll
        for (int o = 0; o < NOUT; ++o) {
#pragma unroll
            for (int s = 16; s > 0; s >>= 1)
                acc[o] += __shfl_xor_sync(0xffffffffu, acc[o], s);
        }
        if (lane == 0) {
#pragma unroll
            for (int o = 0; o < NOUT; ++o) out[row * NOUT + o] = acc[o] + bout[o];
        }
    }

    // ---- safe self-reset: last CTA of mi group (all pollers of mi already done) ----
    __shared__ unsigned s_last;
    if (tid == 0) {
        unsigned old = atomicAdd(&g_fin[mi], 1u);
        s_last = (old == 15u) ? 1u : 0u;
    }
    __syncthreads();
    if (s_last) {
        for (int tt = tid; tt <= TSTEPS; tt += THREADS)
            g_bar[BARIDX(tt, mi)] = 0u;
        __syncthreads();
        if (tid == 0) {
            __threadfence();
            g_fin[mi] = 0u;
        }
    }
}

// ---------------- launch ----------------
extern "C" void kernel_launch(void* const* d_in, const int* in_sizes, int n_in,
                              void* d_out, int out_size) {
    (void)in_sizes; (void)n_in; (void)out_size;
    const float* x    = (const float*)d_in[0];
    const float* W    = (const float*)d_in[1];
    const float* b    = (const float*)d_in[2];
    const float* Wout = (const float*)d_in[3];
    const float* bout = (const float*)d_in[4];
    float* out = (float*)d_out;

    cornn_persist<<<NCTA, THREADS>>>(x, W, b, Wout, bout, out);
}